// round 6
// baseline (speedup 1.0000x reference)
#include <cuda_runtime.h>
#include <math.h>
#include <stdint.h>

// ---------------------------------------------------------------------------
// ResamplerSD3: 8-layer Perceiver resampler.
// mma.sync tf32 GEMMs, cp.async.bulk (TMA path) smem fills, mbarrier pipeline.
// B=32, N1=257, EMB=768, DIM=1024, HEADS=16, DH=64, NQ=64, FF=4096
// ---------------------------------------------------------------------------

#define Bb   32
#define N1   257
#define EMB  768
#define DIM  1024
#define HEADS 16
#define DH   64
#define NQ   64
#define FFI  4096
#define NK   (N1 + NQ)        // 321
#define DEPTH 8

// ---- GEMM tiling: CTA 128(M) x 256(N), BK=32, 3 stages, 512 threads -------
#define STG      3
#define BKT      32
#define A_STRIDE 40                    // floats per A smem row (bank-safe)
#define B_STRIDE 264                   // floats per B smem row (bank-safe)
#define A_SB     (128 * A_STRIDE * 4)  // 20480 B
#define B_SB     (BKT * B_STRIDE * 4)  // 33792 B
#define STAGE_B  (A_SB + B_SB)         // 54272 B
#define CTRL     64
#define GSMEM    (CTRL + STG * STAGE_B)          // 162880 B
#define KT_BYTES (128 * 128 + BKT * 1024)        // 49152 B delivered per kt

// ---------------- static device scratch (no allocations allowed) -----------
__device__ float g_xf   [Bb * N1 * DIM];
__device__ float g_cat  [Bb * NK * DIM];
__device__ float g_lat  [Bb * NQ * DIM];
__device__ float g_lnlat[Bb * NQ * DIM];
__device__ float g_q    [Bb * NQ * DIM];
__device__ float g_kv   [Bb * NK * 2 * DIM];
__device__ float g_o    [Bb * NQ * DIM];
__device__ float g_h    [Bb * NQ * FFI];
__device__ float g_tmp  [Bb * NQ * DIM];
__device__ float g_xr   [Bb * N1 * EMB];      // rounded x
__device__ float g_wt   [102498304];          // all RNA-rounded weights

// offsets into g_wt (floats), original [K,N] layouts
#define OFF_PIN  0
#define OFF_WQ   (OFF_PIN + 768 * 1024)
#define OFF_WKV  (OFF_WQ  + 8 * 1024 * 1024)
#define OFF_WO   (OFF_WKV + 8 * 1024 * 2048)
#define OFF_W1   (OFF_WO  + 8 * 1024 * 1024)
#define OFF_W2   (OFF_W1  + 8 * 1024 * 4096)
#define OFF_POUT (OFF_W2  + 8 * 4096 * 1024)

// ---------------------------------------------------------------------------
__device__ __forceinline__ uint32_t f2tf32(float x)
{
    uint32_t r;
    asm("cvt.rna.tf32.f32 %0, %1;" : "=r"(r) : "f"(x));
    return r;
}
__device__ __forceinline__ float rna_f(float x) { return __uint_as_float(f2tf32(x)); }

__device__ __forceinline__ void mma_tf32(float* d, const uint32_t* a, const uint32_t* b)
{
    asm volatile(
        "mma.sync.aligned.m16n8k8.row.col.f32.tf32.tf32.f32 "
        "{%0,%1,%2,%3}, {%4,%5,%6,%7}, {%8,%9}, {%0,%1,%2,%3};\n"
        : "+f"(d[0]), "+f"(d[1]), "+f"(d[2]), "+f"(d[3])
        : "r"(a[0]), "r"(a[1]), "r"(a[2]), "r"(a[3]), "r"(b[0]), "r"(b[1]));
}

__device__ __forceinline__ void mbar_init(uint32_t a, uint32_t cnt)
{
    asm volatile("mbarrier.init.shared.b64 [%0], %1;" :: "r"(a), "r"(cnt) : "memory");
}
__device__ __forceinline__ void mbar_expect_tx(uint32_t a, uint32_t bytes)
{
    asm volatile("mbarrier.arrive.expect_tx.shared.b64 _, [%0], %1;"
                 :: "r"(a), "r"(bytes) : "memory");
}
__device__ __forceinline__ void mbar_wait(uint32_t a, uint32_t parity)
{
    asm volatile(
        "{\n\t.reg .pred P;\n\t"
        "LW%=:\n\t"
        "mbarrier.try_wait.parity.acquire.cta.shared::cta.b64 P, [%0], %1, 0x989680;\n\t"
        "@!P bra LW%=;\n\t"
        "}" :: "r"(a), "r"(parity) : "memory");
}
__device__ __forceinline__ void bulk_g2s(uint32_t dst, const float* src,
                                         uint32_t bytes, uint32_t mbar)
{
    asm volatile(
        "cp.async.bulk.shared::cluster.global.mbarrier::complete_tx::bytes "
        "[%0], [%1], %2, [%3];"
        :: "r"(dst), "l"(src), "r"(bytes), "r"(mbar) : "memory");
}

// ---------------------------------------------------------------------------
// TF32 GEMM: C[M,N] = A[M,K] @ B[K,N] (+bias)(gelu)(+res)(rna).
// A and B values pre-rounded to tf32 (in-HMMA truncation = identity).
// Grid (N/256, ceil(M/128)), 512 threads (16 warps, 4Mx4N, warp tile 32x64).
// N % 256 == 0, K % 32 == 0 required. M guarded.
// ---------------------------------------------------------------------------
__global__ __launch_bounds__(512, 1)
void tc_gemm(int M, int N, int K,
             const float* __restrict__ A, const float* __restrict__ B,
             float* __restrict__ C, const float* __restrict__ bias,
             const float* __restrict__ res, int do_gelu, int do_rna)
{
    extern __shared__ char smraw[];
    const uint32_t sb = (uint32_t)__cvta_generic_to_shared(smraw);
    const uint32_t sd = sb + CTRL;
    const uint32_t* smU = (const uint32_t*)(smraw + CTRL);

    const int tid  = threadIdx.x;
    const int wid  = tid >> 5;
    const int lane = tid & 31;
    const int gid  = lane >> 2;          // 0..7
    const int tig  = lane & 3;           // 0..3
    const int bx   = blockIdx.x;         // N tile (256)
    const int by   = blockIdx.y;         // M tile (128)

    const int warp_m = (wid & 3) * 32;   // 4 warps along M
    const int warp_n = (wid >> 2) * 64;  // 4 warps along N

    if (tid == 0) {
#pragma unroll
        for (int s = 0; s < STG; s++) mbar_init(sb + 8 * s, 1);
    }
    __syncthreads();

    const int nk = K / BKT;

    // stage fill: thread 0 posts expect_tx; threads 0..127 A rows, 128..159 B rows
    auto fill = [&](int slot, int kt) {
        const uint32_t base = sd + (uint32_t)slot * STAGE_B;
        const uint32_t mbar = sb + 8 * slot;
        if (tid == 0) mbar_expect_tx(mbar, KT_BYTES);
        if (tid < 128) {
            int grow = by * 128 + tid;
            const float* src = A + (size_t)(grow < M ? grow : 0) * K + kt * BKT;
            bulk_g2s(base + (uint32_t)tid * (A_STRIDE * 4), src, 128, mbar);
        } else if (tid < 128 + BKT) {
            int r = tid - 128;
            const float* src = B + (size_t)(kt * BKT + r) * N + bx * 256;
            bulk_g2s(base + A_SB + (uint32_t)r * (B_STRIDE * 4), src, 1024, mbar);
        }
    };

    float acc[2][8][4];
#pragma unroll
    for (int mm = 0; mm < 2; mm++)
#pragma unroll
        for (int nn = 0; nn < 8; nn++)
#pragma unroll
            for (int r = 0; r < 4; r++) acc[mm][nn][r] = 0.0f;

    // prologue
#pragma unroll
    for (int s = 0; s < STG; s++)
        if (s < nk) fill(s, s);

    for (int kt = 0; kt < nk; kt++) {
        const int slot = kt % STG;
        const uint32_t parity = ((uint32_t)(kt / STG)) & 1u;
        mbar_wait(sb + 8 * slot, parity);

        const uint32_t* As_ = smU + (size_t)slot * (STAGE_B / 4);
        const uint32_t* Bs_ = As_ + (A_SB / 4);

#pragma unroll
        for (int ks = 0; ks < 4; ks++) {
            const int kb = ks * 8;
            uint32_t a[2][4], b[8][2];
#pragma unroll
            for (int mm = 0; mm < 2; mm++) {
                int r0 = warp_m + mm * 16 + gid;
                a[mm][0] = As_[r0 * A_STRIDE + kb + tig];
                a[mm][1] = As_[(r0 + 8) * A_STRIDE + kb + tig];
                a[mm][2] = As_[r0 * A_STRIDE + kb + tig + 4];
                a[mm][3] = As_[(r0 + 8) * A_STRIDE + kb + tig + 4];
            }
#pragma unroll
            for (int nn = 0; nn < 8; nn++) {
                int c0 = warp_n + nn * 8 + gid;
                b[nn][0] = Bs_[(kb + tig) * B_STRIDE + c0];
                b[nn][1] = Bs_[(kb + tig + 4) * B_STRIDE + c0];
            }
#pragma unroll
            for (int mm = 0; mm < 2; mm++)
#pragma unroll
                for (int nn = 0; nn < 8; nn++)
                    mma_tf32(acc[mm][nn], a[mm], b[nn]);
        }

        __syncthreads();   // all warps done reading this slot
        if (kt + STG < nk) {
            asm volatile("fence.proxy.async.shared::cta;" ::: "memory");
            fill(slot, kt + STG);
        }
    }

    // ---- epilogue ----
#pragma unroll
    for (int mm = 0; mm < 2; mm++) {
#pragma unroll
        for (int half = 0; half < 2; half++) {
            int row = by * 128 + warp_m + mm * 16 + gid + half * 8;
            if (row >= M) continue;
#pragma unroll
            for (int nn = 0; nn < 8; nn++) {
                int col = bx * 256 + warp_n + nn * 8 + tig * 2;
                float v0 = acc[mm][nn][half * 2 + 0];
                float v1 = acc[mm][nn][half * 2 + 1];
                if (bias) { v0 += bias[col]; v1 += bias[col + 1]; }
                if (do_gelu) {
                    v0 = 0.5f * v0 * (1.0f + erff(v0 * 0.70710678118654752f));
                    v1 = 0.5f * v1 * (1.0f + erff(v1 * 0.70710678118654752f));
                }
                if (res) {
                    v0 += res[(size_t)row * N + col];
                    v1 += res[(size_t)row * N + col + 1];
                }
                if (do_rna) { v0 = rna_f(v0); v1 = rna_f(v1); }
                C[(size_t)row * N + col]     = v0;
                C[(size_t)row * N + col + 1] = v1;
            }
        }
    }
}

// ---------------------------------------------------------------------------
// Round two tensors to tf32 (RNA) in one launch. Sizes in float4 units.
// ---------------------------------------------------------------------------
__global__ void round2_kernel(const float* __restrict__ i1, float* __restrict__ o1,
                              int n1, const float* __restrict__ i2,
                              float* __restrict__ o2, int n2)
{
    int i = blockIdx.x * blockDim.x + threadIdx.x;
    if (i < n1) {
        float4 v = ((const float4*)i1)[i];
        v.x = rna_f(v.x); v.y = rna_f(v.y); v.z = rna_f(v.z); v.w = rna_f(v.w);
        ((float4*)o1)[i] = v;
    } else if (i - n1 < n2) {
        int j = i - n1;
        float4 v = ((const float4*)i2)[j];
        v.x = rna_f(v.x); v.y = rna_f(v.y); v.z = rna_f(v.z); v.w = rna_f(v.w);
        ((float4*)o2)[j] = v;
    }
}

// ---------------------------------------------------------------------------
// LayerNorm over width=1024, optional dual output, optional tf32 rounding.
// ---------------------------------------------------------------------------
__device__ __forceinline__ float2 block_reduce2(float a, float b)
{
    __shared__ float sa[8], sb_[8];
#pragma unroll
    for (int off = 16; off; off >>= 1) {
        a += __shfl_down_sync(0xFFFFFFFFu, a, off);
        b += __shfl_down_sync(0xFFFFFFFFu, b, off);
    }
    int w = threadIdx.x >> 5, l = threadIdx.x & 31;
    if (l == 0) { sa[w] = a; sb_[w] = b; }
    __syncthreads();
    if (w == 0) {
        a = (l < 8) ? sa[l] : 0.f;
        b = (l < 8) ? sb_[l] : 0.f;
#pragma unroll
        for (int off = 4; off; off >>= 1) {
            a += __shfl_down_sync(0xFFFFFFFFu, a, off);
            b += __shfl_down_sync(0xFFFFFFFFu, b, off);
        }
        if (l == 0) { sa[0] = a; sb_[0] = b; }
    }
    __syncthreads();
    return make_float2(sa[0], sb_[0]);
}

__global__ __launch_bounds__(256)
void ln_kernel(const float* __restrict__ in, float* __restrict__ out,
               float* __restrict__ out2,
               const float* __restrict__ g, const float* __restrict__ bta,
               int width, int rpb_in, int rpb_out, int out_off, int do_rna)
{
    int row = blockIdx.x;
    const float* x = in + (size_t)row * width;
    int bi = row / rpb_in, n = row % rpb_in;
    float* y = out + ((size_t)bi * rpb_out + out_off + n) * width;
    float* y2 = out2 ? out2 + (size_t)row * width : nullptr;

    float s = 0.f, s2 = 0.f;
    for (int i = threadIdx.x * 4; i < width; i += blockDim.x * 4) {
        float4 v = *(const float4*)(x + i);
        s  += v.x + v.y + v.z + v.w;
        s2 += v.x * v.x + v.y * v.y + v.z * v.z + v.w * v.w;
    }
    float2 r = block_reduce2(s, s2);
    float mean = r.x / (float)width;
    float var  = r.y / (float)width - mean * mean;
    float rstd = rsqrtf(var + 1e-5f);

    for (int i = threadIdx.x * 4; i < width; i += blockDim.x * 4) {
        float4 v = *(const float4*)(x + i);
        float4 gg = *(const float4*)(g + i);
        float4 bb = *(const float4*)(bta + i);
        float4 o;
        o.x = (v.x - mean) * rstd * gg.x + bb.x;
        o.y = (v.y - mean) * rstd * gg.y + bb.y;
        o.z = (v.z - mean) * rstd * gg.z + bb.z;
        o.w = (v.w - mean) * rstd * gg.w + bb.w;
        if (do_rna) {
            o.x = rna_f(o.x); o.y = rna_f(o.y); o.z = rna_f(o.z); o.w = rna_f(o.w);
        }
        *(float4*)(y + i) = o;
        if (y2) *(float4*)(y2 + i) = o;
    }
}

__global__ void bcast_kernel(const float* __restrict__ latents, float* __restrict__ lat)
{
    size_t i = (size_t)blockIdx.x * blockDim.x + threadIdx.x;
    size_t tot = (size_t)Bb * NQ * DIM;
    if (i < tot) lat[i] = latents[i % ((size_t)NQ * DIM)];
}

// ---------------------------------------------------------------------------
// Attention: per block (b, h, q-tile of 16 rows). fp32; output RNA-rounded.
// ---------------------------------------------------------------------------
__global__ __launch_bounds__(256)
void attn_kernel(const float* __restrict__ q,
                 const float* __restrict__ kv,
                 float* __restrict__ o)
{
    __shared__ float qs[16][DH];
    __shared__ float sc[16][NK];

    int blk = blockIdx.x;
    int qt = blk & 3;
    int h  = (blk >> 2) & 15;
    int b  = blk >> 6;

    const float* qbase = q + ((size_t)b * NQ + qt * 16) * DIM + h * DH;
    for (int i = threadIdx.x; i < 16 * DH; i += 256) {
        int r = i >> 6, c = i & 63;
        qs[r][c] = qbase[(size_t)r * DIM + c];
    }
    __syncthreads();

    const float* kbase = kv + (size_t)b * NK * (2 * DIM) + h * DH;
    const float* vbase = kbase + DIM;

    for (int idx = threadIdx.x; idx < 16 * NK; idx += 256) {
        int r = idx / NK, kk = idx % NK;
        const float* krow = kbase + (size_t)kk * (2 * DIM);
        float acc = 0.f;
#pragma unroll
        for (int d = 0; d < DH; d += 4) {
            float4 k4 = *(const float4*)(krow + d);
            acc += qs[r][d] * k4.x + qs[r][d + 1] * k4.y
                 + qs[r][d + 2] * k4.z + qs[r][d + 3] * k4.w;
        }
        sc[r][kk] = acc * 0.125f;
    }
    __syncthreads();

    int warp = threadIdx.x >> 5, lane = threadIdx.x & 31;
    for (int r = warp * 2; r < warp * 2 + 2; r++) {
        float mx = -1e30f;
        for (int k = lane; k < NK; k += 32) mx = fmaxf(mx, sc[r][k]);
#pragma unroll
        for (int off = 16; off; off >>= 1)
            mx = fmaxf(mx, __shfl_xor_sync(0xFFFFFFFFu, mx, off));
        float sum = 0.f;
        for (int k = lane; k < NK; k += 32) {
            float e = __expf(sc[r][k] - mx);
            sc[r][k] = e;
            sum += e;
        }
#pragma unroll
        for (int off = 16; off; off >>= 1)
            sum += __shfl_xor_sync(0xFFFFFFFFu, sum, off);
        float inv = 1.0f / sum;
        for (int k = lane; k < NK; k += 32) sc[r][k] *= inv;
    }
    __syncthreads();

    int d = threadIdx.x & 63;
    int r0 = threadIdx.x >> 6;
    float acc[4] = {0.f, 0.f, 0.f, 0.f};
    for (int k = 0; k < NK; k++) {
        float vv = vbase[(size_t)k * (2 * DIM) + d];
#pragma unroll
        for (int j = 0; j < 4; j++)
            acc[j] = fmaf(sc[r0 + 4 * j][k], vv, acc[j]);
    }
    float* obase = o + ((size_t)b * NQ + qt * 16) * DIM + h * DH;
#pragma unroll
    for (int j = 0; j < 4; j++)
        obase[(size_t)(r0 + 4 * j) * DIM + d] = rna_f(acc[j]);
}

// ---------------------------------------------------------------------------
static inline void gemm(const float* A, const float* B, float* C,
                        int M, int N, int K,
                        const float* bias, const float* res, int do_gelu, int do_rna)
{
    dim3 grid(N / 256, (M + 127) / 128);
    tc_gemm<<<grid, 512, GSMEM>>>(M, N, K, A, B, C, bias, res, do_gelu, do_rna);
}

extern "C" void kernel_launch(void* const* d_in, const int* in_sizes, int n_in,
                              void* d_out, int out_size)
{
    const float* x          = (const float*)d_in[0];
    const float* latents    = (const float*)d_in[1];
    const float* proj_in_w  = (const float*)d_in[2];
    const float* proj_in_b  = (const float*)d_in[3];
    const float* ln1_g      = (const float*)d_in[4];
    const float* ln1_b      = (const float*)d_in[5];
    const float* ln2_g      = (const float*)d_in[6];
    const float* ln2_b      = (const float*)d_in[7];
    const float* Wq         = (const float*)d_in[8];
    const float* Wkv        = (const float*)d_in[9];
    const float* Wo         = (const float*)d_in[10];
    const float* ff_ln_g    = (const float*)d_in[11];
    const float* ff_ln_b    = (const float*)d_in[12];
    const float* ff_w1      = (const float*)d_in[13];
    const float* ff_w2      = (const float*)d_in[14];
    const float* proj_out_w = (const float*)d_in[15];
    const float* proj_out_b = (const float*)d_in[16];
    const float* norm_out_g = (const float*)d_in[17];
    const float* norm_out_b = (const float*)d_in[18];
    float* out = (float*)d_out;

    cudaFuncSetAttribute(tc_gemm, cudaFuncAttributeMaxDynamicSharedMemorySize, GSMEM);

    float *xf, *cat, *lat, *lnlat, *qb, *kvb, *ob, *hb, *tmp, *xr, *wt;
    cudaGetSymbolAddress((void**)&xf,    g_xf);
    cudaGetSymbolAddress((void**)&cat,   g_cat);
    cudaGetSymbolAddress((void**)&lat,   g_lat);
    cudaGetSymbolAddress((void**)&lnlat, g_lnlat);
    cudaGetSymbolAddress((void**)&qb,    g_q);
    cudaGetSymbolAddress((void**)&kvb,   g_kv);
    cudaGetSymbolAddress((void**)&ob,    g_o);
    cudaGetSymbolAddress((void**)&hb,    g_h);
    cudaGetSymbolAddress((void**)&tmp,   g_tmp);
    cudaGetSymbolAddress((void**)&xr,    g_xr);
    cudaGetSymbolAddress((void**)&wt,    g_wt);

    const int Mx = Bb * N1;   // 8224
    const int Ml = Bb * NQ;   // 2048
    const int Mc = Bb * NK;   // 10272

    // ---- prep (launches #0..#4): RNA-round all weights + x; bcast latents --
    {
        // #0: Wq + Wo (2M + 2M float4)
        int n1 = 8 * DIM * DIM / 4, n2 = 8 * DIM * DIM / 4;
        round2_kernel<<<(n1 + n2 + 255) / 256, 256>>>(
            Wq, wt + OFF_WQ, n1, Wo, wt + OFF_WO, n2);
        // #1: Wkv + W1
        n1 = 8 * DIM * 2 * DIM / 4; n2 = 8 * DIM * FFI / 4;
        round2_kernel<<<(n1 + n2 + 255) / 256, 256>>>(
            Wkv, wt + OFF_WKV, n1, ff_w1, wt + OFF_W1, n2);
        // #2: W2 + proj_out_w
        n1 = 8 * FFI * DIM / 4; n2 = DIM * DIM / 4;
        round2_kernel<<<(n1 + n2 + 255) / 256, 256>>>(
            ff_w2, wt + OFF_W2, n1, proj_out_w, wt + OFF_POUT, n2);
        // #3: proj_in_w + x
        n1 = EMB * DIM / 4; n2 = Bb * N1 * EMB / 4;
        round2_kernel<<<(n1 + n2 + 255) / 256, 256>>>(
            proj_in_w, wt + OFF_PIN, n1, x, xr, n2);
        // #4: broadcast latents
        size_t tot = (size_t)Bb * NQ * DIM;
        bcast_kernel<<<(int)((tot + 255) / 256), 256>>>(latents, lat);
    }

    // #5: proj_in GEMM (profiled by ncu -s 5 -c 1)
    gemm(xr, wt + OFF_PIN, xf, Mx, DIM, EMB, proj_in_b, nullptr, 0, 0);

    for (int i = 0; i < DEPTH; i++) {
        const float* wq  = wt + OFF_WQ  + (size_t)i * DIM * DIM;
        const float* wkv = wt + OFF_WKV + (size_t)i * DIM * 2 * DIM;
        const float* wo  = wt + OFF_WO  + (size_t)i * DIM * DIM;
        const float* w1  = wt + OFF_W1  + (size_t)i * DIM * FFI;
        const float* w2  = wt + OFF_W2  + (size_t)i * FFI * DIM;

        // ln(xf) -> cat rows [0,257)  (rounded: feeds kv gemm)
        ln_kernel<<<Mx, 256>>>(xf, cat, nullptr,
                               ln1_g + (size_t)i * DIM, ln1_b + (size_t)i * DIM,
                               DIM, N1, NK, 0, 1);
        // ln(lat) -> cat rows [257,321) AND lnlat (rounded: feeds kv + q)
        ln_kernel<<<Ml, 256>>>(lat, cat, lnlat,
                               ln2_g + (size_t)i * DIM, ln2_b + (size_t)i * DIM,
                               DIM, NQ, NK, N1, 1);

        gemm(lnlat, wq, qb, Ml, DIM, DIM, nullptr, nullptr, 0, 0);       // q
        gemm(cat, wkv, kvb, Mc, 2 * DIM, DIM, nullptr, nullptr, 0, 0);   // kv

        attn_kernel<<<Bb * HEADS * 4, 256>>>(qb, kvb, ob);               // ob (rna)

        gemm(ob, wo, lat, Ml, DIM, DIM, nullptr, lat, 0, 0);             // lat += o@Wo

        ln_kernel<<<Ml, 256>>>(lat, lnlat, nullptr,
                               ff_ln_g + (size_t)i * DIM, ff_ln_b + (size_t)i * DIM,
                               DIM, NQ, NQ, 0, 1);
        gemm(lnlat, w1, hb, Ml, FFI, DIM, nullptr, nullptr, 1, 1);       // gelu+rna
        gemm(hb, w2, lat, Ml, DIM, FFI, nullptr, lat, 0, 0);             // lat += h@W2
    }

    // round lat for proj_out A-side, then proj_out + final LN
    {
        int n4 = Bb * NQ * DIM / 4;
        round2_kernel<<<(n4 + 255) / 256, 256>>>(lat, lnlat, n4, nullptr, nullptr, 0);
    }
    gemm(lnlat, wt + OFF_POUT, tmp, Ml, DIM, DIM, proj_out_b, nullptr, 0, 0);
    ln_kernel<<<Ml, 256>>>(tmp, out, nullptr, norm_out_g, norm_out_b, DIM, NQ, NQ, 0, 0);
}

// round 7
// speedup vs baseline: 1.0125x; 1.0125x over previous
#include <cuda_runtime.h>
#include <math.h>
#include <stdint.h>

// ---------------------------------------------------------------------------
// ResamplerSD3: 8-layer Perceiver resampler.
// mma.sync tf32 GEMMs, cp.async.bulk smem fills, two tile configs to kill
// wave quantization (128x256 for big GEMMs, 64x128 @2 CTA/SM for small ones).
// ---------------------------------------------------------------------------

#define Bb   32
#define N1   257
#define EMB  768
#define DIM  1024
#define HEADS 16
#define DH   64
#define NQ   64
#define FFI  4096
#define NK   (N1 + NQ)        // 321
#define DEPTH 8

#define STG  3
#define BKT  32
#define A_STRIDE 40           // floats per A smem row (bank-safe: 32+8)

// ---------------- static device scratch (no allocations allowed) -----------
__device__ float g_xf   [Bb * N1 * DIM];
__device__ float g_cat  [Bb * NK * DIM];
__device__ float g_lat  [Bb * NQ * DIM];
__device__ float g_lnlat[Bb * NQ * DIM];
__device__ float g_q    [Bb * NQ * DIM];
__device__ float g_kv   [Bb * NK * 2 * DIM];
__device__ float g_o    [Bb * NQ * DIM];
__device__ float g_h    [Bb * NQ * FFI];
__device__ float g_tmp  [Bb * NQ * DIM];
__device__ float g_xr   [Bb * N1 * EMB];
__device__ float g_wt   [102498304];

#define OFF_PIN  0
#define OFF_WQ   (OFF_PIN + 768 * 1024)
#define OFF_WKV  (OFF_WQ  + 8 * 1024 * 1024)
#define OFF_WO   (OFF_WKV + 8 * 1024 * 2048)
#define OFF_W1   (OFF_WO  + 8 * 1024 * 1024)
#define OFF_W2   (OFF_W1  + 8 * 1024 * 4096)
#define OFF_POUT (OFF_W2  + 8 * 4096 * 1024)

// ---------------------------------------------------------------------------
__device__ __forceinline__ uint32_t f2tf32(float x)
{
    uint32_t r;
    asm("cvt.rna.tf32.f32 %0, %1;" : "=r"(r) : "f"(x));
    return r;
}
__device__ __forceinline__ float rna_f(float x) { return __uint_as_float(f2tf32(x)); }

__device__ __forceinline__ void mma_tf32(float* d, const uint32_t* a, const uint32_t* b)
{
    asm volatile(
        "mma.sync.aligned.m16n8k8.row.col.f32.tf32.tf32.f32 "
        "{%0,%1,%2,%3}, {%4,%5,%6,%7}, {%8,%9}, {%0,%1,%2,%3};\n"
        : "+f"(d[0]), "+f"(d[1]), "+f"(d[2]), "+f"(d[3])
        : "r"(a[0]), "r"(a[1]), "r"(a[2]), "r"(a[3]), "r"(b[0]), "r"(b[1]));
}

__device__ __forceinline__ void mbar_init(uint32_t a, uint32_t cnt)
{
    asm volatile("mbarrier.init.shared.b64 [%0], %1;" :: "r"(a), "r"(cnt) : "memory");
}
__device__ __forceinline__ void mbar_expect_tx(uint32_t a, uint32_t bytes)
{
    asm volatile("mbarrier.arrive.expect_tx.shared.b64 _, [%0], %1;"
                 :: "r"(a), "r"(bytes) : "memory");
}
__device__ __forceinline__ void mbar_wait(uint32_t a, uint32_t parity)
{
    asm volatile(
        "{\n\t.reg .pred P;\n\t"
        "LW%=:\n\t"
        "mbarrier.try_wait.parity.acquire.cta.shared::cta.b64 P, [%0], %1, 0x989680;\n\t"
        "@!P bra LW%=;\n\t"
        "}" :: "r"(a), "r"(parity) : "memory");
}
__device__ __forceinline__ void bulk_g2s(uint32_t dst, const float* src,
                                         uint32_t bytes, uint32_t mbar)
{
    asm volatile(
        "cp.async.bulk.shared::cluster.global.mbarrier::complete_tx::bytes "
        "[%0], [%1], %2, [%3];"
        :: "r"(dst), "l"(src), "r"(bytes), "r"(mbar) : "memory");
}

// ---------------------------------------------------------------------------
// TF32 GEMM template. C[M,N] = A[M,K] @ B[K,N] (+bias)(gelu)(+res)(rna).
// Tile BM x BN, NWM x NWN warps, warp tile 32x64 (identical microkernel for
// all instantiations -> identical accumulation order & rounding).
// ---------------------------------------------------------------------------
template<int BM, int BN, int NWM, int NWN>
__global__ void __launch_bounds__(NWM * NWN * 32)
tc_gemm(int M, int N, int K,
        const float* __restrict__ A, const float* __restrict__ B,
        float* __restrict__ C, const float* __restrict__ bias,
        const float* __restrict__ res, int do_gelu, int do_rna)
{
    constexpr int B_STRIDE = BN + 8;
    constexpr int A_SB = BM * A_STRIDE * 4;
    constexpr int B_SB = BKT * B_STRIDE * 4;
    constexpr int STAGE_B = A_SB + B_SB;
    constexpr int KT_BYTES = BM * 128 + BKT * BN * 4;

    extern __shared__ char smraw[];
    const uint32_t sb = (uint32_t)__cvta_generic_to_shared(smraw);
    const uint32_t sd = sb + 64;
    const uint32_t* smU = (const uint32_t*)(smraw + 64);

    const int tid  = threadIdx.x;
    const int wid  = tid >> 5;
    const int lane = tid & 31;
    const int gid  = lane >> 2;
    const int tig  = lane & 3;
    const int bx   = blockIdx.x;
    const int by   = blockIdx.y;

    const int warp_m = (wid % NWM) * 32;
    const int warp_n = (wid / NWM) * 64;

    if (tid == 0) {
#pragma unroll
        for (int s = 0; s < STG; s++) mbar_init(sb + 8 * s, 1);
    }
    __syncthreads();

    const int nk = K / BKT;

    auto fill = [&](int slot, int kt) {
        const uint32_t base = sd + (uint32_t)slot * STAGE_B;
        const uint32_t mbar = sb + 8 * slot;
        if (tid == 0) mbar_expect_tx(mbar, KT_BYTES);
        if (tid < BM) {
            int grow = by * BM + tid;
            const float* src = A + (size_t)(grow < M ? grow : 0) * K + kt * BKT;
            bulk_g2s(base + (uint32_t)tid * (A_STRIDE * 4), src, 128, mbar);
        } else if (tid < BM + BKT) {
            int r = tid - BM;
            const float* src = B + (size_t)(kt * BKT + r) * N + bx * BN;
            bulk_g2s(base + A_SB + (uint32_t)r * (B_STRIDE * 4), src, BN * 4, mbar);
        }
    };

    float acc[2][8][4];
#pragma unroll
    for (int mm = 0; mm < 2; mm++)
#pragma unroll
        for (int nn = 0; nn < 8; nn++)
#pragma unroll
            for (int r = 0; r < 4; r++) acc[mm][nn][r] = 0.0f;

#pragma unroll
    for (int s = 0; s < STG; s++)
        if (s < nk) fill(s, s);

    for (int kt = 0; kt < nk; kt++) {
        const int slot = kt % STG;
        const uint32_t parity = ((uint32_t)(kt / STG)) & 1u;
        mbar_wait(sb + 8 * slot, parity);

        const uint32_t* As_ = smU + (size_t)slot * (STAGE_B / 4);
        const uint32_t* Bs_ = As_ + (A_SB / 4);

#pragma unroll
        for (int ks = 0; ks < 4; ks++) {
            const int kb = ks * 8;
            uint32_t a[2][4], b[8][2];
#pragma unroll
            for (int mm = 0; mm < 2; mm++) {
                int r0 = warp_m + mm * 16 + gid;
                a[mm][0] = As_[r0 * A_STRIDE + kb + tig];
                a[mm][1] = As_[(r0 + 8) * A_STRIDE + kb + tig];
                a[mm][2] = As_[r0 * A_STRIDE + kb + tig + 4];
                a[mm][3] = As_[(r0 + 8) * A_STRIDE + kb + tig + 4];
            }
#pragma unroll
            for (int nn = 0; nn < 8; nn++) {
                int c0 = warp_n + nn * 8 + gid;
                b[nn][0] = Bs_[(kb + tig) * B_STRIDE + c0];
                b[nn][1] = Bs_[(kb + tig + 4) * B_STRIDE + c0];
            }
#pragma unroll
            for (int mm = 0; mm < 2; mm++)
#pragma unroll
                for (int nn = 0; nn < 8; nn++)
                    mma_tf32(acc[mm][nn], a[mm], b[nn]);
        }

        __syncthreads();
        if (kt + STG < nk) {
            asm volatile("fence.proxy.async.shared::cta;" ::: "memory");
            fill(slot, kt + STG);
        }
    }

    // ---- epilogue ----
#pragma unroll
    for (int mm = 0; mm < 2; mm++) {
#pragma unroll
        for (int half = 0; half < 2; half++) {
            int row = by * BM + warp_m + mm * 16 + gid + half * 8;
            if (row >= M) continue;
#pragma unroll
            for (int nn = 0; nn < 8; nn++) {
                int col = bx * BN + warp_n + nn * 8 + tig * 2;
                float v0 = acc[mm][nn][half * 2 + 0];
                float v1 = acc[mm][nn][half * 2 + 1];
                if (bias) { v0 += bias[col]; v1 += bias[col + 1]; }
                if (do_gelu) {
                    v0 = 0.5f * v0 * (1.0f + erff(v0 * 0.70710678118654752f));
                    v1 = 0.5f * v1 * (1.0f + erff(v1 * 0.70710678118654752f));
                }
                if (res) {
                    v0 += res[(size_t)row * N + col];
                    v1 += res[(size_t)row * N + col + 1];
                }
                if (do_rna) { v0 = rna_f(v0); v1 = rna_f(v1); }
                C[(size_t)row * N + col]     = v0;
                C[(size_t)row * N + col + 1] = v1;
            }
        }
    }
}

// smem sizes per instantiation
#define SMEM_BIG   (64 + STG * (128 * A_STRIDE * 4 + BKT * (256 + 8) * 4))
#define SMEM_SMALL (64 + STG * (64  * A_STRIDE * 4 + BKT * (128 + 8) * 4))

// ---------------------------------------------------------------------------
__global__ void round2_kernel(const float* __restrict__ i1, float* __restrict__ o1,
                              int n1, const float* __restrict__ i2,
                              float* __restrict__ o2, int n2)
{
    int i = blockIdx.x * blockDim.x + threadIdx.x;
    if (i < n1) {
        float4 v = ((const float4*)i1)[i];
        v.x = rna_f(v.x); v.y = rna_f(v.y); v.z = rna_f(v.z); v.w = rna_f(v.w);
        ((float4*)o1)[i] = v;
    } else if (i - n1 < n2) {
        int j = i - n1;
        float4 v = ((const float4*)i2)[j];
        v.x = rna_f(v.x); v.y = rna_f(v.y); v.z = rna_f(v.z); v.w = rna_f(v.w);
        ((float4*)o2)[j] = v;
    }
}

// ---------------------------------------------------------------------------
__device__ __forceinline__ float2 block_reduce2(float a, float b)
{
    __shared__ float sa[8], sb_[8];
#pragma unroll
    for (int off = 16; off; off >>= 1) {
        a += __shfl_down_sync(0xFFFFFFFFu, a, off);
        b += __shfl_down_sync(0xFFFFFFFFu, b, off);
    }
    int w = threadIdx.x >> 5, l = threadIdx.x & 31;
    if (l == 0) { sa[w] = a; sb_[w] = b; }
    __syncthreads();
    if (w == 0) {
        a = (l < 8) ? sa[l] : 0.f;
        b = (l < 8) ? sb_[l] : 0.f;
#pragma unroll
        for (int off = 4; off; off >>= 1) {
            a += __shfl_down_sync(0xFFFFFFFFu, a, off);
            b += __shfl_down_sync(0xFFFFFFFFu, b, off);
        }
        if (l == 0) { sa[0] = a; sb_[0] = b; }
    }
    __syncthreads();
    return make_float2(sa[0], sb_[0]);
}

__global__ __launch_bounds__(256)
void ln_kernel(const float* __restrict__ in, float* __restrict__ out,
               float* __restrict__ out2,
               const float* __restrict__ g, const float* __restrict__ bta,
               int width, int rpb_in, int rpb_out, int out_off, int do_rna)
{
    int row = blockIdx.x;
    const float* x = in + (size_t)row * width;
    int bi = row / rpb_in, n = row % rpb_in;
    float* y = out + ((size_t)bi * rpb_out + out_off + n) * width;
    float* y2 = out2 ? out2 + (size_t)row * width : nullptr;

    float s = 0.f, s2 = 0.f;
    for (int i = threadIdx.x * 4; i < width; i += blockDim.x * 4) {
        float4 v = *(const float4*)(x + i);
        s  += v.x + v.y + v.z + v.w;
        s2 += v.x * v.x + v.y * v.y + v.z * v.z + v.w * v.w;
    }
    float2 r = block_reduce2(s, s2);
    float mean = r.x / (float)width;
    float var  = r.y / (float)width - mean * mean;
    float rstd = rsqrtf(var + 1e-5f);

    for (int i = threadIdx.x * 4; i < width; i += blockDim.x * 4) {
        float4 v = *(const float4*)(x + i);
        float4 gg = *(const float4*)(g + i);
        float4 bb = *(const float4*)(bta + i);
        float4 o;
        o.x = (v.x - mean) * rstd * gg.x + bb.x;
        o.y = (v.y - mean) * rstd * gg.y + bb.y;
        o.z = (v.z - mean) * rstd * gg.z + bb.z;
        o.w = (v.w - mean) * rstd * gg.w + bb.w;
        if (do_rna) {
            o.x = rna_f(o.x); o.y = rna_f(o.y); o.z = rna_f(o.z); o.w = rna_f(o.w);
        }
        *(float4*)(y + i) = o;
        if (y2) *(float4*)(y2 + i) = o;
    }
}

__global__ void bcast_kernel(const float* __restrict__ latents, float* __restrict__ lat)
{
    size_t i = (size_t)blockIdx.x * blockDim.x + threadIdx.x;
    size_t tot = (size_t)Bb * NQ * DIM;
    if (i < tot) lat[i] = latents[i % ((size_t)NQ * DIM)];
}

// ---------------------------------------------------------------------------
__global__ __launch_bounds__(256)
void attn_kernel(const float* __restrict__ q,
                 const float* __restrict__ kv,
                 float* __restrict__ o)
{
    __shared__ float qs[16][DH];
    __shared__ float sc[16][NK];

    int blk = blockIdx.x;
    int qt = blk & 3;
    int h  = (blk >> 2) & 15;
    int b  = blk >> 6;

    const float* qbase = q + ((size_t)b * NQ + qt * 16) * DIM + h * DH;
    for (int i = threadIdx.x; i < 16 * DH; i += 256) {
        int r = i >> 6, c = i & 63;
        qs[r][c] = qbase[(size_t)r * DIM + c];
    }
    __syncthreads();

    const float* kbase = kv + (size_t)b * NK * (2 * DIM) + h * DH;
    const float* vbase = kbase + DIM;

    for (int idx = threadIdx.x; idx < 16 * NK; idx += 256) {
        int r = idx / NK, kk = idx % NK;
        const float* krow = kbase + (size_t)kk * (2 * DIM);
        float acc = 0.f;
#pragma unroll
        for (int d = 0; d < DH; d += 4) {
            float4 k4 = *(const float4*)(krow + d);
            acc += qs[r][d] * k4.x + qs[r][d + 1] * k4.y
                 + qs[r][d + 2] * k4.z + qs[r][d + 3] * k4.w;
        }
        sc[r][kk] = acc * 0.125f;
    }
    __syncthreads();

    int warp = threadIdx.x >> 5, lane = threadIdx.x & 31;
    for (int r = warp * 2; r < warp * 2 + 2; r++) {
        float mx = -1e30f;
        for (int k = lane; k < NK; k += 32) mx = fmaxf(mx, sc[r][k]);
#pragma unroll
        for (int off = 16; off; off >>= 1)
            mx = fmaxf(mx, __shfl_xor_sync(0xFFFFFFFFu, mx, off));
        float sum = 0.f;
        for (int k = lane; k < NK; k += 32) {
            float e = __expf(sc[r][k] - mx);
            sc[r][k] = e;
            sum += e;
        }
#pragma unroll
        for (int off = 16; off; off >>= 1)
            sum += __shfl_xor_sync(0xFFFFFFFFu, sum, off);
        float inv = 1.0f / sum;
        for (int k = lane; k < NK; k += 32) sc[r][k] *= inv;
    }
    __syncthreads();

    int d = threadIdx.x & 63;
    int r0 = threadIdx.x >> 6;
    float acc[4] = {0.f, 0.f, 0.f, 0.f};
    for (int k = 0; k < NK; k++) {
        float vv = vbase[(size_t)k * (2 * DIM) + d];
#pragma unroll
        for (int j = 0; j < 4; j++)
            acc[j] = fmaf(sc[r0 + 4 * j][k], vv, acc[j]);
    }
    float* obase = o + ((size_t)b * NQ + qt * 16) * DIM + h * DH;
#pragma unroll
    for (int j = 0; j < 4; j++)
        obase[(size_t)(r0 + 4 * j) * DIM + d] = rna_f(acc[j]);
}

// ---------------------------------------------------------------------------
static inline void gemm_big(const float* A, const float* B, float* C,
                            int M, int N, int K,
                            const float* bias, const float* res, int gelu, int rna)
{
    dim3 grid(N / 256, (M + 127) / 128);
    tc_gemm<128, 256, 4, 4><<<grid, 512, SMEM_BIG>>>(M, N, K, A, B, C, bias, res, gelu, rna);
}
static inline void gemm_small(const float* A, const float* B, float* C,
                              int M, int N, int K,
                              const float* bias, const float* res, int gelu, int rna)
{
    dim3 grid(N / 128, (M + 63) / 64);
    tc_gemm<64, 128, 2, 2><<<grid, 128, SMEM_SMALL>>>(M, N, K, A, B, C, bias, res, gelu, rna);
}

extern "C" void kernel_launch(void* const* d_in, const int* in_sizes, int n_in,
                              void* d_out, int out_size)
{
    const float* x          = (const float*)d_in[0];
    const float* latents    = (const float*)d_in[1];
    const float* proj_in_w  = (const float*)d_in[2];
    const float* proj_in_b  = (const float*)d_in[3];
    const float* ln1_g      = (const float*)d_in[4];
    const float* ln1_b      = (const float*)d_in[5];
    const float* ln2_g      = (const float*)d_in[6];
    const float* ln2_b      = (const float*)d_in[7];
    const float* Wq         = (const float*)d_in[8];
    const float* Wkv        = (const float*)d_in[9];
    const float* Wo         = (const float*)d_in[10];
    const float* ff_ln_g    = (const float*)d_in[11];
    const float* ff_ln_b    = (const float*)d_in[12];
    const float* ff_w1      = (const float*)d_in[13];
    const float* ff_w2      = (const float*)d_in[14];
    const float* proj_out_w = (const float*)d_in[15];
    const float* proj_out_b = (const float*)d_in[16];
    const float* norm_out_g = (const float*)d_in[17];
    const float* norm_out_b = (const float*)d_in[18];
    float* out = (float*)d_out;

    cudaFuncSetAttribute((const void*)tc_gemm<128, 256, 4, 4>,
                         cudaFuncAttributeMaxDynamicSharedMemorySize, SMEM_BIG);
    cudaFuncSetAttribute((const void*)tc_gemm<64, 128, 2, 2>,
                         cudaFuncAttributeMaxDynamicSharedMemorySize, SMEM_SMALL);

    float *xf, *cat, *lat, *lnlat, *qb, *kvb, *ob, *hb, *tmp, *xr, *wt;
    cudaGetSymbolAddress((void**)&xf,    g_xf);
    cudaGetSymbolAddress((void**)&cat,   g_cat);
    cudaGetSymbolAddress((void**)&lat,   g_lat);
    cudaGetSymbolAddress((void**)&lnlat, g_lnlat);
    cudaGetSymbolAddress((void**)&qb,    g_q);
    cudaGetSymbolAddress((void**)&kvb,   g_kv);
    cudaGetSymbolAddress((void**)&ob,    g_o);
    cudaGetSymbolAddress((void**)&hb,    g_h);
    cudaGetSymbolAddress((void**)&tmp,   g_tmp);
    cudaGetSymbolAddress((void**)&xr,    g_xr);
    cudaGetSymbolAddress((void**)&wt,    g_wt);

    const int Mx = Bb * N1;   // 8224
    const int Ml = Bb * NQ;   // 2048
    const int Mc = Bb * NK;   // 10272

    // ---- prep, ordered so launch #3 is the proj_in GEMM (ncu target) ----
    {
        // #0: proj_in_w + x
        int n1 = EMB * DIM / 4, n2 = Bb * N1 * EMB / 4;
        round2_kernel<<<(n1 + n2 + 255) / 256, 256>>>(
            proj_in_w, wt + OFF_PIN, n1, x, xr, n2);
        // #1: bcast latents
        size_t tot = (size_t)Bb * NQ * DIM;
        bcast_kernel<<<(int)((tot + 255) / 256), 256>>>(latents, lat);
        // #2: Wq + Wkv
        n1 = 8 * DIM * DIM / 4; n2 = 8 * DIM * 2 * DIM / 4;
        round2_kernel<<<(n1 + n2 + 255) / 256, 256>>>(
            Wq, wt + OFF_WQ, n1, Wkv, wt + OFF_WKV, n2);
    }

    // #3: proj_in GEMM
    gemm_big(xr, wt + OFF_PIN, xf, Mx, DIM, EMB, proj_in_b, nullptr, 0, 0);

    {
        // #4: Wo + W1
        int n1 = 8 * DIM * DIM / 4, n2 = 8 * DIM * FFI / 4;
        round2_kernel<<<(n1 + n2 + 255) / 256, 256>>>(
            Wo, wt + OFF_WO, n1, ff_w1, wt + OFF_W1, n2);
        // #5: W2 + proj_out_w
        n1 = 8 * FFI * DIM / 4; n2 = DIM * DIM / 4;
        round2_kernel<<<(n1 + n2 + 255) / 256, 256>>>(
            ff_w2, wt + OFF_W2, n1, proj_out_w, wt + OFF_POUT, n2);
    }

    for (int i = 0; i < DEPTH; i++) {
        const float* wq  = wt + OFF_WQ  + (size_t)i * DIM * DIM;
        const float* wkv = wt + OFF_WKV + (size_t)i * DIM * 2 * DIM;
        const float* wo  = wt + OFF_WO  + (size_t)i * DIM * DIM;
        const float* w1  = wt + OFF_W1  + (size_t)i * DIM * FFI;
        const float* w2  = wt + OFF_W2  + (size_t)i * FFI * DIM;

        ln_kernel<<<Mx, 256>>>(xf, cat, nullptr,
                               ln1_g + (size_t)i * DIM, ln1_b + (size_t)i * DIM,
                               DIM, N1, NK, 0, 1);
        ln_kernel<<<Ml, 256>>>(lat, cat, lnlat,
                               ln2_g + (size_t)i * DIM, ln2_b + (size_t)i * DIM,
                               DIM, NQ, NK, N1, 1);

        gemm_small(lnlat, wq, qb, Ml, DIM, DIM, nullptr, nullptr, 0, 0);   // q
        gemm_big(cat, wkv, kvb, Mc, 2 * DIM, DIM, nullptr, nullptr, 0, 0); // kv

        attn_kernel<<<Bb * HEADS * 4, 256>>>(qb, kvb, ob);

        gemm_small(ob, wo, lat, Ml, DIM, DIM, nullptr, lat, 0, 0);         // lat += o@Wo

        ln_kernel<<<Ml, 256>>>(lat, lnlat, nullptr,
                               ff_ln_g + (size_t)i * DIM, ff_ln_b + (size_t)i * DIM,
                               DIM, NQ, NQ, 0, 1);
        gemm_big(lnlat, w1, hb, Ml, FFI, DIM, nullptr, nullptr, 1, 1);     // gelu+rna
        gemm_small(hb, w2, lat, Ml, DIM, FFI, nullptr, lat, 0, 0);         // lat += h@W2
    }

    {
        int n4 = Bb * NQ * DIM / 4;
        round2_kernel<<<(n4 + 255) / 256, 256>>>(lat, lnlat, n4, nullptr, nullptr, 0);
    }
    gemm_small(lnlat, wt + OFF_POUT, tmp, Ml, DIM, DIM, proj_out_b, nullptr, 0, 0);
    ln_kernel<<<Ml, 256>>>(tmp, out, nullptr, norm_out_g, norm_out_b, DIM, NQ, NQ, 0, 0);
}